// round 5
// baseline (speedup 1.0000x reference)
#include <cuda_runtime.h>

#define NN 100000
#define NE 2500000
#define NG 1000
#define HD 32
#define SCAN_B 512
#define NB ((NN + SCAN_B - 1) / SCAN_B)   // 196

// ---- scratch (__device__ globals; allocation-free) ----
// Never passed as kernel arguments from host; referenced directly in device code.
__device__ int   g_is64;                          // 1 if index inputs are int64
__device__ __align__(16) float g_deg[NN];         // weighted degree -> dinv (in place)
__device__ __align__(16) float g_sn[NN];          // self-loop norm = dinv^2
__device__ __align__(16) int   g_row[NE];         // src (int32 copy)
__device__ __align__(16) int   g_col[NE];         // dst (int32 copy)
__device__ __align__(16) int   g_cnt[NN];         // in-degree histogram
__device__ __align__(16) int   g_scani[NN];       // per-block inclusive scan
__device__ __align__(16) int   g_bsum[256];       // block totals
__device__ __align__(16) int   g_bscan[256];      // scanned block totals
__device__ __align__(16) int   g_off[NN];         // CSR start offsets
__device__ __align__(16) int   g_cur[NN];         // fill cursors
__device__ __align__(16) int   g_erow[NE];        // CSR src indices
__device__ __align__(16) float g_enrm[NE];        // CSR edge norms
__device__ __align__(16) float g_A[NN * HD];
__device__ __align__(16) float g_B[NN * HD];
__device__ __align__(16) float g_gsum[NG * HD];
__device__ __align__(16) float g_gcnt[NG];

// Load index element e from an array that is either int32 or int64.
__device__ __forceinline__ int ldidx(const void* p, long long e) {
    if (g_is64) return (int)((const long long*)p)[e];
    return ((const int*)p)[e];
}

// Detect index width: int64 values < 2^31 have all-zero high words, so when
// viewed as int32, words 1,3,5,... are zero. For genuine int32 edge indices
// (uniform in [0,1e5)) the chance that 32 consecutive odd words are all zero
// is ~1e-160. Single thread; deterministic.
__global__ void k_detect(const void* ei) {
    const int* p = (const int*)ei;
    int z = 0;
#pragma unroll
    for (int j = 1; j < 64; j += 2) z |= p[j];
    g_is64 = (z == 0) ? 1 : 0;
}

__global__ void k_init() {
    int t = blockIdx.x * blockDim.x + threadIdx.x;
    if (t < NN) { g_deg[t] = 0.f; g_cnt[t] = 0; }
    if (t < NG * HD) g_gsum[t] = 0.f;
    if (t < NG) g_gcnt[t] = 0.f;
}

// degree + histogram + index conversion, one pass over edges
__global__ void k_deg_hist(const void* __restrict__ ei, const float* __restrict__ ew) {
    int e = blockIdx.x * blockDim.x + threadIdx.x;
    if (e >= NE) return;
    int r = ldidx(ei, e);
    int c = ldidx(ei, (long long)NE + e);
    g_row[e] = r;
    g_col[e] = c;
    atomicAdd(&g_deg[c], ew[e]);
    atomicAdd(&g_cnt[c], 1);
}

__global__ void k_dinv() {
    int i = blockIdx.x * blockDim.x + threadIdx.x;
    if (i >= NN) return;
    float r = rsqrtf(g_deg[i] + 1.0f);   // +1 = self-loop weight (deg >= 0)
    g_deg[i] = r;
    g_sn[i] = r * r;
}

// ---- 3-stage exclusive prefix scan of g_cnt -> g_off ----
__global__ void k_scan1() {
    __shared__ int s[SCAN_B];
    int tid = threadIdx.x;
    int i = blockIdx.x * SCAN_B + tid;
    s[tid] = (i < NN) ? g_cnt[i] : 0;
    __syncthreads();
#pragma unroll
    for (int off = 1; off < SCAN_B; off <<= 1) {
        int v = (tid >= off) ? s[tid - off] : 0;
        __syncthreads();
        s[tid] += v;
        __syncthreads();
    }
    if (i < NN) g_scani[i] = s[tid];
    if (tid == SCAN_B - 1) g_bsum[blockIdx.x] = s[tid];
}

__global__ void k_scan2() {
    __shared__ int s[256];
    int tid = threadIdx.x;
    s[tid] = (tid < NB) ? g_bsum[tid] : 0;
    __syncthreads();
#pragma unroll
    for (int off = 1; off < 256; off <<= 1) {
        int v = (tid >= off) ? s[tid - off] : 0;
        __syncthreads();
        s[tid] += v;
        __syncthreads();
    }
    g_bscan[tid] = s[tid];
}

__global__ void k_scan3() {
    int i = blockIdx.x * blockDim.x + threadIdx.x;
    if (i >= NN) return;
    int b = i / SCAN_B;
    int add = (b > 0) ? g_bscan[b - 1] : 0;
    int excl = add + g_scani[i] - g_cnt[i];
    g_off[i] = excl;
    g_cur[i] = excl;
}

// CSR fill: edge -> slot within its destination bucket; also compute norm
__global__ void k_fill(const float* __restrict__ ew) {
    int e = blockIdx.x * blockDim.x + threadIdx.x;
    if (e >= NE) return;
    int r = g_row[e];
    int c = g_col[e];
    int p = atomicAdd(&g_cur[c], 1);
    g_erow[p] = r;
    g_enrm[p] = g_deg[r] * ew[e] * g_deg[c];
}

// Layer-1 matmul: A = x @ W1 ; warp per node, lane = out feature
__global__ void k_mm1(const float* __restrict__ x, const float* __restrict__ W1) {
    int t = blockIdx.x * blockDim.x + threadIdx.x;
    int i = t >> 5, f = t & 31;
    if (i >= NN) return;
    float acc = 0.f;
#pragma unroll
    for (int k = 0; k < 4; k++)
        acc += __ldg(&x[i * 4 + k]) * __ldg(&W1[k * HD + f]);
    g_A[i * HD + f] = acc;
}

// Fused layer: per node i (one warp, lane = feature):
//   v = relu( sum_{e in CSR[i]} nrm_e * src[row_e] + sn[i]*src[i] + bias )
//   dst[i] = v @ W    (32x32 matmul via warp shuffles, W staged in smem)
template <bool SRC_IS_A>
__global__ void k_gather_fused(const float* __restrict__ bias, const float* __restrict__ W) {
    const float* src = SRC_IS_A ? g_A : g_B;
    float*       dst = SRC_IS_A ? g_B : g_A;
    __shared__ float Ws[HD * HD];
    int tid = threadIdx.x;
    for (int k = tid; k < HD * HD; k += blockDim.x) Ws[k] = W[k];
    __syncthreads();
    int t = blockIdx.x * blockDim.x + tid;
    int i = t >> 5, lane = t & 31;
    if (i >= NN) return;

    int beg = g_off[i];
    int cnt = g_cnt[i];
    float acc = 0.f;
    for (int base = 0; base < cnt; base += 32) {
        int idx = base + lane;
        int r = 0; float w = 0.f;
        if (idx < cnt) { r = g_erow[beg + idx]; w = g_enrm[beg + idx]; }
        int nb = min(32, cnt - base);
        for (int k = 0; k < nb; k++) {
            int   rk = __shfl_sync(0xffffffffu, r, k);
            float wk = __shfl_sync(0xffffffffu, w, k);
            acc += wk * src[(size_t)rk * HD + lane];   // coalesced 128B row read
        }
    }
    float v = acc + g_sn[i] * src[(size_t)i * HD + lane] + __ldg(&bias[lane]);
    v = fmaxf(v, 0.f);

    float o = 0.f;
#pragma unroll
    for (int k = 0; k < HD; k++) {
        float vk = __shfl_sync(0xffffffffu, v, k);
        o += vk * Ws[k * HD + lane];
    }
    dst[(size_t)i * HD + lane] = o;
}

// Layer-3 gather (src = g_A; no relu, no matmul) fused with mean-pool accumulation.
__global__ void k_gather_pool(const float* __restrict__ bias,
                              const void* __restrict__ batch) {
    const float* src = g_A;
    int t = blockIdx.x * blockDim.x + threadIdx.x;
    int i = t >> 5, lane = t & 31;
    if (i >= NN) return;

    int beg = g_off[i];
    int cnt = g_cnt[i];
    float acc = 0.f;
    for (int base = 0; base < cnt; base += 32) {
        int idx = base + lane;
        int r = 0; float w = 0.f;
        if (idx < cnt) { r = g_erow[beg + idx]; w = g_enrm[beg + idx]; }
        int nb = min(32, cnt - base);
        for (int k = 0; k < nb; k++) {
            int   rk = __shfl_sync(0xffffffffu, r, k);
            float wk = __shfl_sync(0xffffffffu, w, k);
            acc += wk * src[(size_t)rk * HD + lane];
        }
    }
    float v = acc + g_sn[i] * src[(size_t)i * HD + lane] + __ldg(&bias[lane]);
    int g = ldidx(batch, i);
    atomicAdd(&g_gsum[g * HD + lane], v);
    if (lane == 0) atomicAdd(&g_gcnt[g], 1.0f);
}

// Head: softmax((pooled_mean @ lin_w) + lin_b) per graph.
__global__ void k_head(const float* __restrict__ lw, const float* __restrict__ lb,
                       float* __restrict__ out) {
    int g = blockIdx.x * blockDim.x + threadIdx.x;
    if (g >= NG) return;
    float inv = 1.0f / fmaxf(g_gcnt[g], 1.0f);
    float l0 = __ldg(&lb[0]), l1 = __ldg(&lb[1]), l2 = __ldg(&lb[2]);
#pragma unroll 8
    for (int k = 0; k < HD; k++) {
        float p = g_gsum[g * HD + k] * inv;
        l0 += p * __ldg(&lw[k * 3 + 0]);
        l1 += p * __ldg(&lw[k * 3 + 1]);
        l2 += p * __ldg(&lw[k * 3 + 2]);
    }
    float m = fmaxf(l0, fmaxf(l1, l2));
    float e0 = expf(l0 - m), e1 = expf(l1 - m), e2 = expf(l2 - m);
    float s = 1.0f / (e0 + e1 + e2);
    out[g * 3 + 0] = e0 * s;
    out[g * 3 + 1] = e1 * s;
    out[g * 3 + 2] = e2 * s;
}

extern "C" void kernel_launch(void* const* d_in, const int* in_sizes, int n_in,
                              void* d_out, int out_size) {
    const float* x     = (const float*)d_in[0];
    const void*  ei    = d_in[1];
    const float* ew    = (const float*)d_in[2];
    const void*  batch = d_in[3];
    const float* W1    = (const float*)d_in[4];
    const float* b1    = (const float*)d_in[5];
    const float* W2    = (const float*)d_in[6];
    const float* b2    = (const float*)d_in[7];
    const float* W3    = (const float*)d_in[8];
    const float* b3    = (const float*)d_in[9];
    const float* lw    = (const float*)d_in[10];
    const float* lb    = (const float*)d_in[11];
    float* out = (float*)d_out;

    const int B = 256;
    const int gbN  = (NN + B - 1) / B;
    const int gbE  = (NE + B - 1) / B;
    const int gbNH = (NN * HD + B - 1) / B;   // warp-per-node grids

    k_detect<<<1, 1>>>(ei);
    k_init<<<gbN, B>>>();                      // covers NN (> NG*HD, > NG)
    k_deg_hist<<<gbE, B>>>(ei, ew);
    k_dinv<<<gbN, B>>>();
    k_scan1<<<NB, SCAN_B>>>();
    k_scan2<<<1, 256>>>();
    k_scan3<<<gbN, B>>>();
    k_fill<<<gbE, B>>>(ew);

    k_mm1<<<gbNH, B>>>(x, W1);
    k_gather_fused<true><<<gbNH, B>>>(b1, W2);    // L1 agg (g_A) + relu + @W2 -> g_B
    k_gather_fused<false><<<gbNH, B>>>(b2, W3);   // L2 agg (g_B) + relu + @W3 -> g_A
    k_gather_pool<<<gbNH, B>>>(b3, batch);        // L3 agg (g_A) + pool
    k_head<<<(NG + B - 1) / B, B>>>(lw, lb, out);
}

// round 6
// speedup vs baseline: 1.1985x; 1.1985x over previous
#include <cuda_runtime.h>

#define NN 100000
#define NE 2500000
#define NG 1000
#define HD 32
#define SCAN_B 512
#define NB ((NN + SCAN_B - 1) / SCAN_B)   // 196

// ---- scratch (__device__ globals; allocation-free) ----
// Never passed as kernel args from host; referenced directly in device code.
__device__ int   g_is64;                          // 1 if index inputs are int64
__device__ __align__(16) float g_deg[NN];         // weighted degree -> dinv (in place)
__device__ __align__(16) float g_sn[NN];          // self-loop norm = dinv^2
__device__ __align__(16) int   g_row[NE];         // src (int32 copy)
__device__ __align__(16) int   g_col[NE];         // dst (int32 copy)
__device__ __align__(16) int   g_cnt[NN];         // in-degree histogram
__device__ __align__(16) int   g_scani[NN];       // per-block inclusive scan
__device__ __align__(16) int   g_bsum[256];       // block totals
__device__ __align__(16) int   g_bscan[256];      // scanned block totals
__device__ __align__(16) int   g_off[NN];         // CSR start offsets
__device__ __align__(16) int   g_cur[NN];         // fill cursors
__device__ __align__(16) int2  g_csr[NE];         // packed {src, __float_as_int(norm)}
__device__ __align__(16) float g_A[NN * HD];
__device__ __align__(16) float g_B[NN * HD];
__device__ __align__(16) float g_gsum[NG * HD];
__device__ __align__(16) float g_gcnt[NG];

__device__ __forceinline__ int ldidx(const void* p, long long e) {
    if (g_is64) return (int)((const long long*)p)[e];
    return ((const int*)p)[e];
}

// init + index-width detection (thread 0 of block 0).
// int64 values < 2^31 have all-zero high words -> odd int32 words all zero.
__global__ void k_init(const void* ei) {
    int t = blockIdx.x * blockDim.x + threadIdx.x;
    if (t == 0) {
        const int* p = (const int*)ei;
        int z = 0;
#pragma unroll
        for (int j = 1; j < 64; j += 2) z |= p[j];
        g_is64 = (z == 0) ? 1 : 0;
    }
    if (t < NN) { g_deg[t] = 0.f; g_cnt[t] = 0; }
    if (t < NG * HD) g_gsum[t] = 0.f;
    if (t < NG) g_gcnt[t] = 0.f;
}

// degree + histogram + index conversion, one pass over edges
__global__ void k_deg_hist(const void* __restrict__ ei, const float* __restrict__ ew) {
    int e = blockIdx.x * blockDim.x + threadIdx.x;
    if (e >= NE) return;
    int r = ldidx(ei, e);
    int c = ldidx(ei, (long long)NE + e);
    g_row[e] = r;
    g_col[e] = c;
    atomicAdd(&g_deg[c], ew[e]);
    atomicAdd(&g_cnt[c], 1);
}

// ---- 3-stage exclusive prefix scan of g_cnt -> g_off (dinv fused into stage 3) ----
__global__ void k_scan1() {
    __shared__ int s[SCAN_B];
    int tid = threadIdx.x;
    int i = blockIdx.x * SCAN_B + tid;
    s[tid] = (i < NN) ? g_cnt[i] : 0;
    __syncthreads();
#pragma unroll
    for (int off = 1; off < SCAN_B; off <<= 1) {
        int v = (tid >= off) ? s[tid - off] : 0;
        __syncthreads();
        s[tid] += v;
        __syncthreads();
    }
    if (i < NN) g_scani[i] = s[tid];
    if (tid == SCAN_B - 1) g_bsum[blockIdx.x] = s[tid];
}

__global__ void k_scan2() {
    __shared__ int s[256];
    int tid = threadIdx.x;
    s[tid] = (tid < NB) ? g_bsum[tid] : 0;
    __syncthreads();
#pragma unroll
    for (int off = 1; off < 256; off <<= 1) {
        int v = (tid >= off) ? s[tid - off] : 0;
        __syncthreads();
        s[tid] += v;
        __syncthreads();
    }
    g_bscan[tid] = s[tid];
}

__global__ void k_scan3() {
    int i = blockIdx.x * blockDim.x + threadIdx.x;
    if (i >= NN) return;
    int b = i / SCAN_B;
    int add = (b > 0) ? g_bscan[b - 1] : 0;
    int excl = add + g_scani[i] - g_cnt[i];
    g_off[i] = excl;
    g_cur[i] = excl;
    float r = rsqrtf(g_deg[i] + 1.0f);   // fused dinv (+1 = self-loop weight)
    g_deg[i] = r;
    g_sn[i] = r * r;
}

// CSR fill: packed int2 {src, norm} -> one STG.64 per edge (half the random sectors)
__global__ void k_fill(const float* __restrict__ ew) {
    int e = blockIdx.x * blockDim.x + threadIdx.x;
    if (e >= NE) return;
    int r = g_row[e];
    int c = g_col[e];
    int p = atomicAdd(&g_cur[c], 1);
    float nrm = g_deg[r] * ew[e] * g_deg[c];
    g_csr[p] = make_int2(r, __float_as_int(nrm));
}

// Layer-1 matmul: A = x @ W1 ; warp per node, lane = out feature
__global__ void k_mm1(const float* __restrict__ x, const float* __restrict__ W1) {
    int t = blockIdx.x * blockDim.x + threadIdx.x;
    int i = t >> 5, f = t & 31;
    if (i >= NN) return;
    float acc = 0.f;
#pragma unroll
    for (int k = 0; k < 4; k++)
        acc += __ldg(&x[i * 4 + k]) * __ldg(&W1[k * HD + f]);
    g_A[i * HD + f] = acc;
}

// Vectorized gather for node i: warp = 4 edge-groups x 8 lanes.
// grp = lane>>3 handles every 4th edge; sub = lane&7 covers features sub*4..sub*4+3.
// Returns v = agg + sn*self + bias (pre-activation), replicated across all 4 groups.
__device__ __forceinline__ float4 gather_node(const float* __restrict__ src, int i,
                                              int grp, int sub,
                                              const float* __restrict__ bias) {
    const float4* src4 = reinterpret_cast<const float4*>(src);
    int beg = g_off[i];
    int cnt = g_cnt[i];
    float4 acc = make_float4(0.f, 0.f, 0.f, 0.f);
    int e = 0;
#pragma unroll 4
    for (; e + 4 <= cnt; e += 4) {
        int2 ce = g_csr[beg + e + grp];
        float w = __int_as_float(ce.y);
        float4 v = src4[(size_t)ce.x * 8 + sub];
        acc.x = fmaf(w, v.x, acc.x);
        acc.y = fmaf(w, v.y, acc.y);
        acc.z = fmaf(w, v.z, acc.z);
        acc.w = fmaf(w, v.w, acc.w);
    }
    int rem = cnt - e;
    if (rem > 0) {
        int g2 = min(grp, rem - 1);              // clamp: valid load, zero weight
        int2 ce = g_csr[beg + e + g2];
        float w = (grp < rem) ? __int_as_float(ce.y) : 0.f;
        float4 v = src4[(size_t)ce.x * 8 + sub];
        acc.x = fmaf(w, v.x, acc.x);
        acc.y = fmaf(w, v.y, acc.y);
        acc.z = fmaf(w, v.z, acc.z);
        acc.w = fmaf(w, v.w, acc.w);
    }
    // reduce across the 4 groups -> every lane holds the full sum (replicated)
#pragma unroll
    for (int d = 8; d <= 16; d <<= 1) {
        acc.x += __shfl_xor_sync(0xffffffffu, acc.x, d);
        acc.y += __shfl_xor_sync(0xffffffffu, acc.y, d);
        acc.z += __shfl_xor_sync(0xffffffffu, acc.z, d);
        acc.w += __shfl_xor_sync(0xffffffffu, acc.w, d);
    }
    float4 sv = src4[(size_t)i * 8 + sub];
    float sn = g_sn[i];
    float4 b4 = __ldg(&reinterpret_cast<const float4*>(bias)[sub]);
    acc.x = fmaf(sn, sv.x, acc.x) + b4.x;
    acc.y = fmaf(sn, sv.y, acc.y) + b4.y;
    acc.z = fmaf(sn, sv.z, acc.z) + b4.z;
    acc.w = fmaf(sn, sv.w, acc.w) + b4.w;
    return acc;
}

// Fused layer: gather + relu + 32x32 matmul (group-split over k) -> dst
template <bool SRC_IS_A>
__global__ void k_layer(const float* __restrict__ bias, const float* __restrict__ W) {
    const float* src = SRC_IS_A ? g_A : g_B;
    float*       dst = SRC_IS_A ? g_B : g_A;
    __shared__ float4 Ws[HD * 8];                 // W[k][f] as float4: Ws[k*8 + sub]
    int tid = threadIdx.x;
    for (int k = tid; k < HD * 8; k += blockDim.x)
        Ws[k] = reinterpret_cast<const float4*>(W)[k];
    __syncthreads();
    int t = blockIdx.x * blockDim.x + tid;
    int i = t >> 5, lane = t & 31, grp = lane >> 3, sub = lane & 7;
    if (i >= NN) return;

    float4 v = gather_node(src, i, grp, sub, bias);
    v.x = fmaxf(v.x, 0.f); v.y = fmaxf(v.y, 0.f);
    v.z = fmaxf(v.z, 0.f); v.w = fmaxf(v.w, 0.f);

    // o[f] = sum_k v[k] * W[k][f]; group grp handles k in [grp*8, grp*8+8)
    float4 o = make_float4(0.f, 0.f, 0.f, 0.f);
#pragma unroll
    for (int j = 0; j < 8; j++) {
        int srcLane = grp * 10 + (j >> 2);        // = grp*8 + ((grp*8+j)>>2)
        float comp = ((j & 3) == 0) ? v.x : ((j & 3) == 1) ? v.y
                   : ((j & 3) == 2) ? v.z : v.w;
        float vk = __shfl_sync(0xffffffffu, comp, srcLane);
        float4 w4 = Ws[(grp * 8 + j) * 8 + sub];
        o.x = fmaf(vk, w4.x, o.x);
        o.y = fmaf(vk, w4.y, o.y);
        o.z = fmaf(vk, w4.z, o.z);
        o.w = fmaf(vk, w4.w, o.w);
    }
#pragma unroll
    for (int d = 8; d <= 16; d <<= 1) {
        o.x += __shfl_xor_sync(0xffffffffu, o.x, d);
        o.y += __shfl_xor_sync(0xffffffffu, o.y, d);
        o.z += __shfl_xor_sync(0xffffffffu, o.z, d);
        o.w += __shfl_xor_sync(0xffffffffu, o.w, d);
    }
    if (grp == 0)
        reinterpret_cast<float4*>(dst)[(size_t)i * 8 + sub] = o;   // 128B coalesced
}

// Layer-3: gather (no relu, no matmul) + mean-pool accumulation
__global__ void k_gather_pool(const float* __restrict__ bias,
                              const void* __restrict__ batch) {
    int t = blockIdx.x * blockDim.x + threadIdx.x;
    int i = t >> 5, lane = t & 31, grp = lane >> 3, sub = lane & 7;
    if (i >= NN) return;
    float4 v = gather_node(g_A, i, grp, sub, bias);
    int g = ldidx(batch, i);
    if (grp == 0) {
        float* dstp = &g_gsum[g * HD + sub * 4];
        atomicAdd(dstp + 0, v.x);
        atomicAdd(dstp + 1, v.y);
        atomicAdd(dstp + 2, v.z);
        atomicAdd(dstp + 3, v.w);
    }
    if (lane == 0) atomicAdd(&g_gcnt[g], 1.0f);
}

// Head: softmax((pooled_mean @ lin_w) + lin_b) per graph.
__global__ void k_head(const float* __restrict__ lw, const float* __restrict__ lb,
                       float* __restrict__ out) {
    int g = blockIdx.x * blockDim.x + threadIdx.x;
    if (g >= NG) return;
    float inv = 1.0f / fmaxf(g_gcnt[g], 1.0f);
    float l0 = __ldg(&lb[0]), l1 = __ldg(&lb[1]), l2 = __ldg(&lb[2]);
#pragma unroll 8
    for (int k = 0; k < HD; k++) {
        float p = g_gsum[g * HD + k] * inv;
        l0 += p * __ldg(&lw[k * 3 + 0]);
        l1 += p * __ldg(&lw[k * 3 + 1]);
        l2 += p * __ldg(&lw[k * 3 + 2]);
    }
    float m = fmaxf(l0, fmaxf(l1, l2));
    float e0 = expf(l0 - m), e1 = expf(l1 - m), e2 = expf(l2 - m);
    float s = 1.0f / (e0 + e1 + e2);
    out[g * 3 + 0] = e0 * s;
    out[g * 3 + 1] = e1 * s;
    out[g * 3 + 2] = e2 * s;
}

extern "C" void kernel_launch(void* const* d_in, const int* in_sizes, int n_in,
                              void* d_out, int out_size) {
    const float* x     = (const float*)d_in[0];
    const void*  ei    = d_in[1];
    const float* ew    = (const float*)d_in[2];
    const void*  batch = d_in[3];
    const float* W1    = (const float*)d_in[4];
    const float* b1    = (const float*)d_in[5];
    const float* W2    = (const float*)d_in[6];
    const float* b2    = (const float*)d_in[7];
    const float* W3    = (const float*)d_in[8];
    const float* b3    = (const float*)d_in[9];
    const float* lw    = (const float*)d_in[10];
    const float* lb    = (const float*)d_in[11];
    float* out = (float*)d_out;

    const int B = 256;
    const int gbN  = (NN + B - 1) / B;
    const int gbE  = (NE + B - 1) / B;
    const int gbNH = (NN * HD + B - 1) / B;   // warp-per-node grids

    k_init<<<gbN, B>>>(ei);                   // covers NN; fuses index-width detect
    k_deg_hist<<<gbE, B>>>(ei, ew);
    k_scan1<<<NB, SCAN_B>>>();
    k_scan2<<<1, 256>>>();
    k_scan3<<<gbN, B>>>();                    // fuses dinv
    k_fill<<<gbE, B>>>(ew);

    k_mm1<<<gbNH, B>>>(x, W1);
    k_layer<true><<<gbNH, B>>>(b1, W2);       // L1 agg (g_A) + relu + @W2 -> g_B
    k_layer<false><<<gbNH, B>>>(b2, W3);      // L2 agg (g_B) + relu + @W3 -> g_A
    k_gather_pool<<<gbNH, B>>>(b3, batch);    // L3 agg (g_A) + pool
    k_head<<<(NG + B - 1) / B, B>>>(lw, lb, out);
}

// round 7
// speedup vs baseline: 1.3785x; 1.1502x over previous
#include <cuda_runtime.h>

#define NN 100000
#define NE 2500000
#define NG 1000
#define HD 32
#define SCAN_B 512
#define NB ((NN + SCAN_B - 1) / SCAN_B)   // 196

// ---- scratch (__device__ globals; allocation-free) ----
// Never passed as kernel args from host; referenced directly in device code.
__device__ int   g_is64;                          // 1 if index inputs are int64
__device__ __align__(16) float g_deg[NN];         // weighted degree -> dinv (in place)
__device__ __align__(16) float g_sn[NN];          // self-loop norm = dinv^2
__device__ __align__(16) int   g_cnt[NN];         // in-degree histogram
__device__ __align__(16) int   g_scani[NN];       // per-block inclusive scan
__device__ __align__(16) int   g_bsum[256];       // block totals
__device__ __align__(16) int   g_bscan[256];      // scanned block totals
__device__ __align__(16) int   g_off[NN];         // CSR start offsets
__device__ __align__(16) int   g_cur[NN];         // fill cursors
__device__ __align__(16) int2  g_csr[NE];         // packed {src, __float_as_int(norm)}
__device__ __align__(16) float g_A[NN * HD];
__device__ __align__(16) float g_B[NN * HD];
__device__ __align__(16) float g_gsum[NG * HD];
__device__ __align__(16) float g_gcnt[NG];

__device__ __forceinline__ int ldidx(const void* p, long long e) {
    if (g_is64) return (int)((const long long*)p)[e];
    return ((const int*)p)[e];
}

// init + index-width detection (thread 0).
// int64 values < 2^31 have all-zero high words -> odd int32 words all zero.
__global__ void k_init(const void* ei) {
    int t = blockIdx.x * blockDim.x + threadIdx.x;
    if (t == 0) {
        const int* p = (const int*)ei;
        int z = 0;
#pragma unroll
        for (int j = 1; j < 64; j += 2) z |= p[j];
        g_is64 = (z == 0) ? 1 : 0;
    }
    if (t < NN) { g_deg[t] = 0.f; g_cnt[t] = 0; }
    if (t < NG * HD) g_gsum[t] = 0.f;
    if (t < NG) g_gcnt[t] = 0.f;
}

// degree + histogram: only needs the col half of edge_index
__global__ void k_deg_hist(const void* __restrict__ ei, const float* __restrict__ ew) {
    int e = blockIdx.x * blockDim.x + threadIdx.x;
    if (e >= NE) return;
    int c = ldidx(ei, (long long)NE + e);
    atomicAdd(&g_deg[c], ew[e]);
    atomicAdd(&g_cnt[c], 1);
}

// ---- 3-stage exclusive prefix scan of g_cnt -> g_off (dinv fused into stage 3) ----
__global__ void k_scan1() {
    __shared__ int s[SCAN_B];
    int tid = threadIdx.x;
    int i = blockIdx.x * SCAN_B + tid;
    s[tid] = (i < NN) ? g_cnt[i] : 0;
    __syncthreads();
#pragma unroll
    for (int off = 1; off < SCAN_B; off <<= 1) {
        int v = (tid >= off) ? s[tid - off] : 0;
        __syncthreads();
        s[tid] += v;
        __syncthreads();
    }
    if (i < NN) g_scani[i] = s[tid];
    if (tid == SCAN_B - 1) g_bsum[blockIdx.x] = s[tid];
}

__global__ void k_scan2() {
    __shared__ int s[256];
    int tid = threadIdx.x;
    s[tid] = (tid < NB) ? g_bsum[tid] : 0;
    __syncthreads();
#pragma unroll
    for (int off = 1; off < 256; off <<= 1) {
        int v = (tid >= off) ? s[tid - off] : 0;
        __syncthreads();
        s[tid] += v;
        __syncthreads();
    }
    g_bscan[tid] = s[tid];
}

__global__ void k_scan3() {
    int i = blockIdx.x * blockDim.x + threadIdx.x;
    if (i >= NN) return;
    int b = i / SCAN_B;
    int add = (b > 0) ? g_bscan[b - 1] : 0;
    int excl = add + g_scani[i] - g_cnt[i];
    g_off[i] = excl;
    g_cur[i] = excl;
    float r = rsqrtf(g_deg[i] + 1.0f);   // fused dinv (+1 = self-loop weight)
    g_deg[i] = r;
    g_sn[i] = r * r;
}

// CSR fill: re-read edge_index; packed int2 {src, norm} -> one STG.64 per edge
__global__ void k_fill(const void* __restrict__ ei, const float* __restrict__ ew) {
    int e = blockIdx.x * blockDim.x + threadIdx.x;
    if (e >= NE) return;
    int r = ldidx(ei, e);
    int c = ldidx(ei, (long long)NE + e);
    int p = atomicAdd(&g_cur[c], 1);
    float nrm = g_deg[r] * ew[e] * g_deg[c];
    g_csr[p] = make_int2(r, __float_as_int(nrm));
}

// Layer 1 (linearity: Ahat(x@W1) = (Ahat x)@W1): gather raw 4-dim x rows (16B!),
// then per-node epilogue: h1 = relu(agg4 @ W1 + b1); out = h1 @ W2 -> g_B.
// Warp per node, each lane handles one edge (lane-strided).
__global__ void k_layer1(const float* __restrict__ x,
                         const float* __restrict__ W1, const float* __restrict__ b1,
                         const float* __restrict__ W2) {
    __shared__ float W1s[4 * HD];
    __shared__ float W2s[HD * HD];
    int tid = threadIdx.x;
    for (int k = tid; k < 4 * HD; k += blockDim.x)  W1s[k] = W1[k];
    for (int k = tid; k < HD * HD; k += blockDim.x) W2s[k] = W2[k];
    __syncthreads();
    int t = blockIdx.x * blockDim.x + tid;
    int i = t >> 5, lane = t & 31;
    if (i >= NN) return;

    const float4* x4 = reinterpret_cast<const float4*>(x);
    int beg = g_off[i];
    int cnt = g_cnt[i];
    float4 acc = make_float4(0.f, 0.f, 0.f, 0.f);
    for (int e = lane; e < cnt; e += 32) {
        int2 ce = g_csr[beg + e];
        float w = __int_as_float(ce.y);
        float4 xv = __ldg(&x4[ce.x]);
        acc.x = fmaf(w, xv.x, acc.x);
        acc.y = fmaf(w, xv.y, acc.y);
        acc.z = fmaf(w, xv.z, acc.z);
        acc.w = fmaf(w, xv.w, acc.w);
    }
#pragma unroll
    for (int d = 1; d < 32; d <<= 1) {
        acc.x += __shfl_xor_sync(0xffffffffu, acc.x, d);
        acc.y += __shfl_xor_sync(0xffffffffu, acc.y, d);
        acc.z += __shfl_xor_sync(0xffffffffu, acc.z, d);
        acc.w += __shfl_xor_sync(0xffffffffu, acc.w, d);
    }
    float4 xi = __ldg(&x4[i]);
    float sn = g_sn[i];
    acc.x = fmaf(sn, xi.x, acc.x);
    acc.y = fmaf(sn, xi.y, acc.y);
    acc.z = fmaf(sn, xi.z, acc.z);
    acc.w = fmaf(sn, xi.w, acc.w);

    // h1[lane] = relu(agg4 . W1[:,lane] + b1[lane])
    float h = __ldg(&b1[lane]);
    h = fmaf(acc.x, W1s[0 * HD + lane], h);
    h = fmaf(acc.y, W1s[1 * HD + lane], h);
    h = fmaf(acc.z, W1s[2 * HD + lane], h);
    h = fmaf(acc.w, W1s[3 * HD + lane], h);
    h = fmaxf(h, 0.f);

    // o[lane] = sum_k h_k * W2[k][lane]
    float o = 0.f;
#pragma unroll
    for (int k = 0; k < HD; k++) {
        float hk = __shfl_sync(0xffffffffu, h, k);
        o = fmaf(hk, W2s[k * HD + lane], o);
    }
    g_B[(size_t)i * HD + lane] = o;   // 128B coalesced per warp
}

// Vectorized gather for node i: warp = 4 edge-groups x 8 lanes; 8 edges/iter main loop.
// Returns v = agg + sn*self + bias (pre-activation), replicated across all 4 groups.
__device__ __forceinline__ float4 gather_node(const float* __restrict__ src, int i,
                                              int grp, int sub,
                                              const float* __restrict__ bias) {
    const float4* src4 = reinterpret_cast<const float4*>(src);
    int beg = g_off[i];
    int cnt = g_cnt[i];
    float4 acc = make_float4(0.f, 0.f, 0.f, 0.f);
    float4 acc2 = make_float4(0.f, 0.f, 0.f, 0.f);
    int e = 0;
#pragma unroll 2
    for (; e + 8 <= cnt; e += 8) {               // two independent chains per lane
        int2 ce0 = g_csr[beg + e + grp];
        int2 ce1 = g_csr[beg + e + 4 + grp];
        float w0 = __int_as_float(ce0.y);
        float w1 = __int_as_float(ce1.y);
        float4 v0 = src4[(size_t)ce0.x * 8 + sub];
        float4 v1 = src4[(size_t)ce1.x * 8 + sub];
        acc.x  = fmaf(w0, v0.x, acc.x);  acc.y  = fmaf(w0, v0.y, acc.y);
        acc.z  = fmaf(w0, v0.z, acc.z);  acc.w  = fmaf(w0, v0.w, acc.w);
        acc2.x = fmaf(w1, v1.x, acc2.x); acc2.y = fmaf(w1, v1.y, acc2.y);
        acc2.z = fmaf(w1, v1.z, acc2.z); acc2.w = fmaf(w1, v1.w, acc2.w);
    }
    acc.x += acc2.x; acc.y += acc2.y; acc.z += acc2.z; acc.w += acc2.w;
    if (e + 4 <= cnt) {
        int2 ce = g_csr[beg + e + grp];
        float w = __int_as_float(ce.y);
        float4 v = src4[(size_t)ce.x * 8 + sub];
        acc.x = fmaf(w, v.x, acc.x); acc.y = fmaf(w, v.y, acc.y);
        acc.z = fmaf(w, v.z, acc.z); acc.w = fmaf(w, v.w, acc.w);
        e += 4;
    }
    int rem = cnt - e;
    if (rem > 0) {
        int g2 = min(grp, rem - 1);              // clamp: valid load, zero weight
        int2 ce = g_csr[beg + e + g2];
        float w = (grp < rem) ? __int_as_float(ce.y) : 0.f;
        float4 v = src4[(size_t)ce.x * 8 + sub];
        acc.x = fmaf(w, v.x, acc.x); acc.y = fmaf(w, v.y, acc.y);
        acc.z = fmaf(w, v.z, acc.z); acc.w = fmaf(w, v.w, acc.w);
    }
#pragma unroll
    for (int d = 8; d <= 16; d <<= 1) {          // reduce across the 4 groups
        acc.x += __shfl_xor_sync(0xffffffffu, acc.x, d);
        acc.y += __shfl_xor_sync(0xffffffffu, acc.y, d);
        acc.z += __shfl_xor_sync(0xffffffffu, acc.z, d);
        acc.w += __shfl_xor_sync(0xffffffffu, acc.w, d);
    }
    float4 sv = src4[(size_t)i * 8 + sub];
    float sn = g_sn[i];
    float4 b4 = __ldg(&reinterpret_cast<const float4*>(bias)[sub]);
    acc.x = fmaf(sn, sv.x, acc.x) + b4.x;
    acc.y = fmaf(sn, sv.y, acc.y) + b4.y;
    acc.z = fmaf(sn, sv.z, acc.z) + b4.z;
    acc.w = fmaf(sn, sv.w, acc.w) + b4.w;
    return acc;
}

// Layer 2: gather g_B + relu + 32x32 matmul (group-split over k) -> g_A
__global__ void k_layer2(const float* __restrict__ bias, const float* __restrict__ W) {
    __shared__ float4 Ws[HD * 8];                 // W[k][f] as float4: Ws[k*8 + sub]
    int tid = threadIdx.x;
    for (int k = tid; k < HD * 8; k += blockDim.x)
        Ws[k] = reinterpret_cast<const float4*>(W)[k];
    __syncthreads();
    int t = blockIdx.x * blockDim.x + tid;
    int i = t >> 5, lane = t & 31, grp = lane >> 3, sub = lane & 7;
    if (i >= NN) return;

    float4 v = gather_node(g_B, i, grp, sub, bias);
    v.x = fmaxf(v.x, 0.f); v.y = fmaxf(v.y, 0.f);
    v.z = fmaxf(v.z, 0.f); v.w = fmaxf(v.w, 0.f);

    float4 o = make_float4(0.f, 0.f, 0.f, 0.f);
#pragma unroll
    for (int j = 0; j < 8; j++) {
        int srcLane = grp * 10 + (j >> 2);        // = grp*8 + ((grp*8+j)>>2)
        float comp = ((j & 3) == 0) ? v.x : ((j & 3) == 1) ? v.y
                   : ((j & 3) == 2) ? v.z : v.w;
        float vk = __shfl_sync(0xffffffffu, comp, srcLane);
        float4 w4 = Ws[(grp * 8 + j) * 8 + sub];
        o.x = fmaf(vk, w4.x, o.x); o.y = fmaf(vk, w4.y, o.y);
        o.z = fmaf(vk, w4.z, o.z); o.w = fmaf(vk, w4.w, o.w);
    }
#pragma unroll
    for (int d = 8; d <= 16; d <<= 1) {
        o.x += __shfl_xor_sync(0xffffffffu, o.x, d);
        o.y += __shfl_xor_sync(0xffffffffu, o.y, d);
        o.z += __shfl_xor_sync(0xffffffffu, o.z, d);
        o.w += __shfl_xor_sync(0xffffffffu, o.w, d);
    }
    if (grp == 0)
        reinterpret_cast<float4*>(g_A)[(size_t)i * 8 + sub] = o;
}

// Layer 3: gather g_A (no relu/matmul) + mean-pool. batch is SORTED: blocks hold
// 8 consecutive nodes; graph-uniform blocks issue 1 atomic per feature.
__global__ void k_gather_pool(const float* __restrict__ bias,
                              const void* __restrict__ batch) {
    __shared__ float s[8][HD];
    __shared__ int sg[8];
    int tid = threadIdx.x;
    int t = blockIdx.x * blockDim.x + tid;
    int i = t >> 5, lane = t & 31, grp = lane >> 3, sub = lane & 7;
    int warpid = tid >> 5;
    // grid is exactly NN/8 blocks; every i < NN
    float4 v = gather_node(g_A, i, grp, sub, bias);
    if (grp == 0)
        *reinterpret_cast<float4*>(&s[warpid][sub * 4]) = v;
    if (lane == 0) sg[warpid] = ldidx(batch, i);
    __syncthreads();
    if (tid < HD) {
        int g0 = sg[0];
        if (g0 == sg[7]) {                        // sorted => all 8 equal
            float sum = 0.f;
#pragma unroll
            for (int w = 0; w < 8; w++) sum += s[w][tid];
            atomicAdd(&g_gsum[g0 * HD + tid], sum);
            if (tid == 0) atomicAdd(&g_gcnt[g0], 8.0f);
        } else {
#pragma unroll
            for (int w = 0; w < 8; w++)
                atomicAdd(&g_gsum[sg[w] * HD + tid], s[w][tid]);
            if (tid == 0) {
#pragma unroll
                for (int w = 0; w < 8; w++) atomicAdd(&g_gcnt[sg[w]], 1.0f);
            }
        }
    }
}

// Head: softmax((pooled_mean @ lin_w) + lin_b) per graph.
__global__ void k_head(const float* __restrict__ lw, const float* __restrict__ lb,
                       float* __restrict__ out) {
    int g = blockIdx.x * blockDim.x + threadIdx.x;
    if (g >= NG) return;
    float inv = 1.0f / fmaxf(g_gcnt[g], 1.0f);
    float l0 = __ldg(&lb[0]), l1 = __ldg(&lb[1]), l2 = __ldg(&lb[2]);
#pragma unroll 8
    for (int k = 0; k < HD; k++) {
        float p = g_gsum[g * HD + k] * inv;
        l0 += p * __ldg(&lw[k * 3 + 0]);
        l1 += p * __ldg(&lw[k * 3 + 1]);
        l2 += p * __ldg(&lw[k * 3 + 2]);
    }
    float m = fmaxf(l0, fmaxf(l1, l2));
    float e0 = expf(l0 - m), e1 = expf(l1 - m), e2 = expf(l2 - m);
    float s = 1.0f / (e0 + e1 + e2);
    out[g * 3 + 0] = e0 * s;
    out[g * 3 + 1] = e1 * s;
    out[g * 3 + 2] = e2 * s;
}

extern "C" void kernel_launch(void* const* d_in, const int* in_sizes, int n_in,
                              void* d_out, int out_size) {
    const float* x     = (const float*)d_in[0];
    const void*  ei    = d_in[1];
    const float* ew    = (const float*)d_in[2];
    const void*  batch = d_in[3];
    const float* W1    = (const float*)d_in[4];
    const float* b1    = (const float*)d_in[5];
    const float* W2    = (const float*)d_in[6];
    const float* b2    = (const float*)d_in[7];
    const float* W3    = (const float*)d_in[8];
    const float* b3    = (const float*)d_in[9];
    const float* lw    = (const float*)d_in[10];
    const float* lb    = (const float*)d_in[11];
    float* out = (float*)d_out;

    const int B = 256;
    const int gbN  = (NN + B - 1) / B;
    const int gbE  = (NE + B - 1) / B;
    const int gbNH = (NN * HD) / B;           // exactly 12500 blocks, 8 nodes each

    k_init<<<gbN, B>>>(ei);
    k_deg_hist<<<gbE, B>>>(ei, ew);
    k_scan1<<<NB, SCAN_B>>>();
    k_scan2<<<1, 256>>>();
    k_scan3<<<gbN, B>>>();
    k_fill<<<gbE, B>>>(ei, ew);

    k_layer1<<<gbNH, B>>>(x, W1, b1, W2);     // gather x (16B rows) + @W1+b1,relu,@W2 -> g_B
    k_layer2<<<gbNH, B>>>(b2, W3);            // gather g_B + relu + @W3 -> g_A
    k_gather_pool<<<gbNH, B>>>(b3, batch);    // gather g_A + sorted-batch pool
    k_head<<<(NG + B - 1) / B, B>>>(lw, lb, out);
}

// round 8
// speedup vs baseline: 1.4589x; 1.0583x over previous
#include <cuda_runtime.h>
#include <cuda_fp16.h>

#define NN 100000
#define NE 2500000
#define NG 1000
#define HD 32
#define SCAN_B 512
#define NB ((NN + SCAN_B - 1) / SCAN_B)   // 196

// ---- scratch (__device__ globals; allocation-free) ----
// Never passed as kernel args from host; referenced directly in device code.
__device__ int   g_is64;                          // 1 if index inputs are int64
__device__ __align__(16) float  g_deg[NN];        // weighted degree -> dinv (in place)
__device__ __align__(16) int    g_cnt[NN];        // in-degree histogram
__device__ __align__(16) int    g_scani[NN];      // per-block inclusive scan
__device__ __align__(16) int    g_bsum[256];      // block totals
__device__ __align__(16) int    g_bscan[256];     // scanned block totals
__device__ __align__(16) int    g_off[NN];        // CSR start offsets
__device__ __align__(16) int    g_cur[NN];        // fill cursors
__device__ __align__(16) int2   g_csr[NE];        // packed {src, __float_as_int(dinv[src]*w)}
__device__ __align__(16) __half g_Ah[NN * HD];    // fp16 feature matrices (64B rows)
__device__ __align__(16) __half g_Bh[NN * HD];
__device__ __align__(16) float  g_gsum[NG * HD];
__device__ __align__(16) float  g_gcnt[NG];

__device__ __forceinline__ int ldidx(const void* p, long long e) {
    if (g_is64) return (int)((const long long*)p)[e];
    return ((const int*)p)[e];
}

// init + index-width detection (thread 0).
// int64 values < 2^31 have all-zero high words -> odd int32 words all zero.
__global__ void k_init(const void* ei) {
    int t = blockIdx.x * blockDim.x + threadIdx.x;
    if (t == 0) {
        const int* p = (const int*)ei;
        int z = 0;
#pragma unroll
        for (int j = 1; j < 64; j += 2) z |= p[j];
        g_is64 = (z == 0) ? 1 : 0;
    }
    if (t < NN) { g_deg[t] = 0.f; g_cnt[t] = 0; }
    if (t < NG * HD) g_gsum[t] = 0.f;
    if (t < NG) g_gcnt[t] = 0.f;
}

// degree + histogram: only needs the col half of edge_index
__global__ void k_deg_hist(const void* __restrict__ ei, const float* __restrict__ ew) {
    int e = blockIdx.x * blockDim.x + threadIdx.x;
    if (e >= NE) return;
    int c = ldidx(ei, (long long)NE + e);
    atomicAdd(&g_deg[c], ew[e]);
    atomicAdd(&g_cnt[c], 1);
}

// ---- 3-stage exclusive prefix scan of g_cnt -> g_off (dinv fused into stage 3) ----
__global__ void k_scan1() {
    __shared__ int s[SCAN_B];
    int tid = threadIdx.x;
    int i = blockIdx.x * SCAN_B + tid;
    s[tid] = (i < NN) ? g_cnt[i] : 0;
    __syncthreads();
#pragma unroll
    for (int off = 1; off < SCAN_B; off <<= 1) {
        int v = (tid >= off) ? s[tid - off] : 0;
        __syncthreads();
        s[tid] += v;
        __syncthreads();
    }
    if (i < NN) g_scani[i] = s[tid];
    if (tid == SCAN_B - 1) g_bsum[blockIdx.x] = s[tid];
}

__global__ void k_scan2() {
    __shared__ int s[256];
    int tid = threadIdx.x;
    s[tid] = (tid < NB) ? g_bsum[tid] : 0;
    __syncthreads();
#pragma unroll
    for (int off = 1; off < 256; off <<= 1) {
        int v = (tid >= off) ? s[tid - off] : 0;
        __syncthreads();
        s[tid] += v;
        __syncthreads();
    }
    g_bscan[tid] = s[tid];
}

__global__ void k_scan3() {
    int i = blockIdx.x * blockDim.x + threadIdx.x;
    if (i >= NN) return;
    int b = i / SCAN_B;
    int add = (b > 0) ? g_bscan[b - 1] : 0;
    int excl = add + g_scani[i] - g_cnt[i];
    g_off[i] = excl;
    g_cur[i] = excl;
    g_deg[i] = rsqrtf(g_deg[i] + 1.0f);   // dinv (+1 = self-loop weight)
}

// CSR fill: store {src, dinv[src]*w}; dinv[dst] applied at gather epilogue.
__global__ void k_fill(const void* __restrict__ ei, const float* __restrict__ ew) {
    int e = blockIdx.x * blockDim.x + threadIdx.x;
    if (e >= NE) return;
    int r = ldidx(ei, e);
    int c = ldidx(ei, (long long)NE + e);
    int p = atomicAdd(&g_cur[c], 1);
    float nrm = g_deg[r] * ew[e];
    g_csr[p] = make_int2(r, __float_as_int(nrm));
}

// Layer 1 (linearity: Ahat(x@W1) = (Ahat x)@W1): gather raw 4-dim fp32 x rows,
// epilogue: agg = dinv_i*(sum + dinv_i*x_i); h1 = relu(agg@W1+b1); g_Bh = fp16(h1@W2).
__global__ void k_layer1(const float* __restrict__ x,
                         const float* __restrict__ W1, const float* __restrict__ b1,
                         const float* __restrict__ W2) {
    __shared__ float W1s[4 * HD];
    __shared__ float W2s[HD * HD];
    int tid = threadIdx.x;
    for (int k = tid; k < 4 * HD; k += blockDim.x)  W1s[k] = W1[k];
    for (int k = tid; k < HD * HD; k += blockDim.x) W2s[k] = W2[k];
    __syncthreads();
    int t = blockIdx.x * blockDim.x + tid;
    int i = t >> 5, lane = t & 31;
    if (i >= NN) return;

    const float4* x4 = reinterpret_cast<const float4*>(x);
    int beg = g_off[i];
    int cnt = g_cnt[i];
    float4 acc = make_float4(0.f, 0.f, 0.f, 0.f);
    for (int e = lane; e < cnt; e += 32) {
        int2 ce = g_csr[beg + e];
        float w = __int_as_float(ce.y);
        float4 xv = __ldg(&x4[ce.x]);
        acc.x = fmaf(w, xv.x, acc.x);
        acc.y = fmaf(w, xv.y, acc.y);
        acc.z = fmaf(w, xv.z, acc.z);
        acc.w = fmaf(w, xv.w, acc.w);
    }
#pragma unroll
    for (int d = 1; d < 32; d <<= 1) {
        acc.x += __shfl_xor_sync(0xffffffffu, acc.x, d);
        acc.y += __shfl_xor_sync(0xffffffffu, acc.y, d);
        acc.z += __shfl_xor_sync(0xffffffffu, acc.z, d);
        acc.w += __shfl_xor_sync(0xffffffffu, acc.w, d);
    }
    float4 xi = __ldg(&x4[i]);
    float dv = g_deg[i];
    acc.x = fmaf(dv, xi.x, acc.x) * dv;
    acc.y = fmaf(dv, xi.y, acc.y) * dv;
    acc.z = fmaf(dv, xi.z, acc.z) * dv;
    acc.w = fmaf(dv, xi.w, acc.w) * dv;

    // h1[lane] = relu(agg4 . W1[:,lane] + b1[lane])
    float h = __ldg(&b1[lane]);
    h = fmaf(acc.x, W1s[0 * HD + lane], h);
    h = fmaf(acc.y, W1s[1 * HD + lane], h);
    h = fmaf(acc.z, W1s[2 * HD + lane], h);
    h = fmaf(acc.w, W1s[3 * HD + lane], h);
    h = fmaxf(h, 0.f);

    // o[lane] = sum_k h_k * W2[k][lane]
    float o = 0.f;
#pragma unroll
    for (int k = 0; k < HD; k++) {
        float hk = __shfl_sync(0xffffffffu, h, k);
        o = fmaf(hk, W2s[k * HD + lane], o);
    }
    g_Bh[(size_t)i * HD + lane] = __float2half_rn(o);   // 64B coalesced per warp
}

// fp16 gather for node i: warp = 4 edge-groups x 8 lanes; each lane loads 8B (4 halves).
// Returns v = dinv_i*(agg + dinv_i*self) + bias, replicated across the 4 groups.
__device__ __forceinline__ float4 gather_node_h(const uint2* __restrict__ src, int i,
                                                int grp, int sub,
                                                const float* __restrict__ bias) {
    int beg = g_off[i];
    int cnt = g_cnt[i];
    float4 acc  = make_float4(0.f, 0.f, 0.f, 0.f);
    float4 acc2 = make_float4(0.f, 0.f, 0.f, 0.f);
    int e = 0;
#pragma unroll 2
    for (; e + 8 <= cnt; e += 8) {               // two independent chains per lane
        int2 ce0 = g_csr[beg + e + grp];
        int2 ce1 = g_csr[beg + e + 4 + grp];
        float w0 = __int_as_float(ce0.y);
        float w1 = __int_as_float(ce1.y);
        uint2 u0 = src[(size_t)ce0.x * 8 + sub];
        uint2 u1 = src[(size_t)ce1.x * 8 + sub];
        float2 a01 = __half22float2(*reinterpret_cast<__half2*>(&u0.x));
        float2 a23 = __half22float2(*reinterpret_cast<__half2*>(&u0.y));
        float2 b01 = __half22float2(*reinterpret_cast<__half2*>(&u1.x));
        float2 b23 = __half22float2(*reinterpret_cast<__half2*>(&u1.y));
        acc.x  = fmaf(w0, a01.x, acc.x);  acc.y  = fmaf(w0, a01.y, acc.y);
        acc.z  = fmaf(w0, a23.x, acc.z);  acc.w  = fmaf(w0, a23.y, acc.w);
        acc2.x = fmaf(w1, b01.x, acc2.x); acc2.y = fmaf(w1, b01.y, acc2.y);
        acc2.z = fmaf(w1, b23.x, acc2.z); acc2.w = fmaf(w1, b23.y, acc2.w);
    }
    acc.x += acc2.x; acc.y += acc2.y; acc.z += acc2.z; acc.w += acc2.w;
    if (e + 4 <= cnt) {
        int2 ce = g_csr[beg + e + grp];
        float w = __int_as_float(ce.y);
        uint2 u = src[(size_t)ce.x * 8 + sub];
        float2 a01 = __half22float2(*reinterpret_cast<__half2*>(&u.x));
        float2 a23 = __half22float2(*reinterpret_cast<__half2*>(&u.y));
        acc.x = fmaf(w, a01.x, acc.x); acc.y = fmaf(w, a01.y, acc.y);
        acc.z = fmaf(w, a23.x, acc.z); acc.w = fmaf(w, a23.y, acc.w);
        e += 4;
    }
    int rem = cnt - e;
    if (rem > 0) {
        int g2 = min(grp, rem - 1);              // clamp: valid load, zero weight
        int2 ce = g_csr[beg + e + g2];
        float w = (grp < rem) ? __int_as_float(ce.y) : 0.f;
        uint2 u = src[(size_t)ce.x * 8 + sub];
        float2 a01 = __half22float2(*reinterpret_cast<__half2*>(&u.x));
        float2 a23 = __half22float2(*reinterpret_cast<__half2*>(&u.y));
        acc.x = fmaf(w, a01.x, acc.x); acc.y = fmaf(w, a01.y, acc.y);
        acc.z = fmaf(w, a23.x, acc.z); acc.w = fmaf(w, a23.y, acc.w);
    }
#pragma unroll
    for (int d = 8; d <= 16; d <<= 1) {          // reduce across the 4 groups
        acc.x += __shfl_xor_sync(0xffffffffu, acc.x, d);
        acc.y += __shfl_xor_sync(0xffffffffu, acc.y, d);
        acc.z += __shfl_xor_sync(0xffffffffu, acc.z, d);
        acc.w += __shfl_xor_sync(0xffffffffu, acc.w, d);
    }
    uint2 us = src[(size_t)i * 8 + sub];
    float2 s01 = __half22float2(*reinterpret_cast<__half2*>(&us.x));
    float2 s23 = __half22float2(*reinterpret_cast<__half2*>(&us.y));
    float dv = g_deg[i];
    float4 b4 = __ldg(&reinterpret_cast<const float4*>(bias)[sub]);
    acc.x = fmaf(fmaf(dv, s01.x, acc.x), dv, b4.x);
    acc.y = fmaf(fmaf(dv, s01.y, acc.y), dv, b4.y);
    acc.z = fmaf(fmaf(dv, s23.x, acc.z), dv, b4.z);
    acc.w = fmaf(fmaf(dv, s23.y, acc.w), dv, b4.w);
    return acc;
}

// Layer 2: gather g_Bh + relu + 32x32 matmul (group-split over k) -> g_Ah (fp16)
__global__ void k_layer2(const float* __restrict__ bias, const float* __restrict__ W) {
    __shared__ float4 Ws[HD * 8];                 // W[k][f] as float4: Ws[k*8 + sub]
    int tid = threadIdx.x;
    for (int k = tid; k < HD * 8; k += blockDim.x)
        Ws[k] = reinterpret_cast<const float4*>(W)[k];
    __syncthreads();
    int t = blockIdx.x * blockDim.x + tid;
    int i = t >> 5, lane = t & 31, grp = lane >> 3, sub = lane & 7;
    if (i >= NN) return;

    float4 v = gather_node_h(reinterpret_cast<const uint2*>(g_Bh), i, grp, sub, bias);
    v.x = fmaxf(v.x, 0.f); v.y = fmaxf(v.y, 0.f);
    v.z = fmaxf(v.z, 0.f); v.w = fmaxf(v.w, 0.f);

    float4 o = make_float4(0.f, 0.f, 0.f, 0.f);
#pragma unroll
    for (int j = 0; j < 8; j++) {
        int srcLane = grp * 10 + (j >> 2);        // = grp*8 + ((grp*8+j)>>2)
        float comp = ((j & 3) == 0) ? v.x : ((j & 3) == 1) ? v.y
                   : ((j & 3) == 2) ? v.z : v.w;
        float vk = __shfl_sync(0xffffffffu, comp, srcLane);
        float4 w4 = Ws[(grp * 8 + j) * 8 + sub];
        o.x = fmaf(vk, w4.x, o.x); o.y = fmaf(vk, w4.y, o.y);
        o.z = fmaf(vk, w4.z, o.z); o.w = fmaf(vk, w4.w, o.w);
    }
#pragma unroll
    for (int d = 8; d <= 16; d <<= 1) {
        o.x += __shfl_xor_sync(0xffffffffu, o.x, d);
        o.y += __shfl_xor_sync(0xffffffffu, o.y, d);
        o.z += __shfl_xor_sync(0xffffffffu, o.z, d);
        o.w += __shfl_xor_sync(0xffffffffu, o.w, d);
    }
    if (grp == 0) {
        __half2 p0 = __floats2half2_rn(o.x, o.y);
        __half2 p1 = __floats2half2_rn(o.z, o.w);
        uint2 st;
        st.x = *reinterpret_cast<unsigned*>(&p0);
        st.y = *reinterpret_cast<unsigned*>(&p1);
        reinterpret_cast<uint2*>(g_Ah)[(size_t)i * 8 + sub] = st;
    }
}

// Layer 3: gather g_Ah (no relu/matmul) + mean-pool. batch is SORTED: blocks hold
// 8 consecutive nodes; graph-uniform blocks issue 1 atomic per feature.
__global__ void k_gather_pool(const float* __restrict__ bias,
                              const void* __restrict__ batch) {
    __shared__ float s[8][HD];
    __shared__ int sg[8];
    int tid = threadIdx.x;
    int t = blockIdx.x * blockDim.x + tid;
    int i = t >> 5, lane = t & 31, grp = lane >> 3, sub = lane & 7;
    int warpid = tid >> 5;
    float4 v = gather_node_h(reinterpret_cast<const uint2*>(g_Ah), i, grp, sub, bias);
    if (grp == 0)
        *reinterpret_cast<float4*>(&s[warpid][sub * 4]) = v;
    if (lane == 0) sg[warpid] = ldidx(batch, i);
    __syncthreads();
    if (tid < HD) {
        int g0 = sg[0];
        if (g0 == sg[7]) {                        // sorted => all 8 equal
            float sum = 0.f;
#pragma unroll
            for (int w = 0; w < 8; w++) sum += s[w][tid];
            atomicAdd(&g_gsum[g0 * HD + tid], sum);
            if (tid == 0) atomicAdd(&g_gcnt[g0], 8.0f);
        } else {
#pragma unroll
            for (int w = 0; w < 8; w++)
                atomicAdd(&g_gsum[sg[w] * HD + tid], s[w][tid]);
            if (tid == 0) {
#pragma unroll
                for (int w = 0; w < 8; w++) atomicAdd(&g_gcnt[sg[w]], 1.0f);
            }
        }
    }
}

// Head: softmax((pooled_mean @ lin_w) + lin_b) per graph.
__global__ void k_head(const float* __restrict__ lw, const float* __restrict__ lb,
                       float* __restrict__ out) {
    int g = blockIdx.x * blockDim.x + threadIdx.x;
    if (g >= NG) return;
    float inv = 1.0f / fmaxf(g_gcnt[g], 1.0f);
    float l0 = __ldg(&lb[0]), l1 = __ldg(&lb[1]), l2 = __ldg(&lb[2]);
#pragma unroll 8
    for (int k = 0; k < HD; k++) {
        float p = g_gsum[g * HD + k] * inv;
        l0 += p * __ldg(&lw[k * 3 + 0]);
        l1 += p * __ldg(&lw[k * 3 + 1]);
        l2 += p * __ldg(&lw[k * 3 + 2]);
    }
    float m = fmaxf(l0, fmaxf(l1, l2));
    float e0 = expf(l0 - m), e1 = expf(l1 - m), e2 = expf(l2 - m);
    float s = 1.0f / (e0 + e1 + e2);
    out[g * 3 + 0] = e0 * s;
    out[g * 3 + 1] = e1 * s;
    out[g * 3 + 2] = e2 * s;
}

extern "C" void kernel_launch(void* const* d_in, const int* in_sizes, int n_in,
                              void* d_out, int out_size) {
    const float* x     = (const float*)d_in[0];
    const void*  ei    = d_in[1];
    const float* ew    = (const float*)d_in[2];
    const void*  batch = d_in[3];
    const float* W1    = (const float*)d_in[4];
    const float* b1    = (const float*)d_in[5];
    const float* W2    = (const float*)d_in[6];
    const float* b2    = (const float*)d_in[7];
    const float* W3    = (const float*)d_in[8];
    const float* b3    = (const float*)d_in[9];
    const float* lw    = (const float*)d_in[10];
    const float* lb    = (const float*)d_in[11];
    float* out = (float*)d_out;

    const int B = 256;
    const int gbN  = (NN + B - 1) / B;
    const int gbE  = (NE + B - 1) / B;
    const int gbNH = (NN * HD) / B;           // exactly 12500 blocks, 8 nodes each

    k_init<<<gbN, B>>>(ei);
    k_deg_hist<<<gbE, B>>>(ei, ew);
    k_scan1<<<NB, SCAN_B>>>();
    k_scan2<<<1, 256>>>();
    k_scan3<<<gbN, B>>>();
    k_fill<<<gbE, B>>>(ei, ew);

    k_layer1<<<gbNH, B>>>(x, W1, b1, W2);     // gather x + @W1+b1,relu,@W2 -> g_Bh (fp16)
    k_layer2<<<gbNH, B>>>(b2, W3);            // gather g_Bh + relu + @W3 -> g_Ah (fp16)
    k_gather_pool<<<gbNH, B>>>(b3, batch);    // gather g_Ah + sorted-batch pool
    k_head<<<(NG + B - 1) / B, B>>>(lw, lb, out);
}